// round 4
// baseline (speedup 1.0000x reference)
#include <cuda_runtime.h>
#include <cstdint>

#define N_NODE 100000
#define N_TOT  102000
#define NFEAT  256
#define NDIM   128
#define E_MAX  1700000

// ---------------------------------------------------------------------------
// Device scratch (allocation-free): CSR build area for both adjacencies
// ---------------------------------------------------------------------------
__device__ int                g_cnt [2][N_TOT];
__device__ int                g_rptr[2][N_TOT];
__device__ int                g_head[2][N_TOT];
__device__ unsigned long long g_rec [2][E_MAX];

// ---------------------------------------------------------------------------
// zero the histogram counters
// ---------------------------------------------------------------------------
__global__ void zero_cnt_kernel() {
    int i = blockIdx.x * blockDim.x + threadIdx.x;
    int n = 2 * N_TOT;
    int stride = gridDim.x * blockDim.x;
    for (int j = i; j < n; j += stride)
        ((int*)g_cnt)[j] = 0;
}

// ---------------------------------------------------------------------------
// histogram of destination rows, both adjacencies in one launch
// ---------------------------------------------------------------------------
__global__ __launch_bounds__(256) void hist_kernel(
    const int* __restrict__ erow1, const int* __restrict__ erow2,
    int E, int perAdj)
{
    int idx = blockIdx.x * blockDim.x + threadIdx.x;
    int a = 0;
    if (idx >= perAdj) { a = 1; idx -= perAdj; if (idx >= perAdj) return; }
    const int* erow = a ? erow2 : erow1;
    int e0 = idx * 4;
    if (e0 + 4 <= E) {
        int4 r4 = *(const int4*)(erow + e0);
        atomicAdd(&g_cnt[a][r4.x], 1);
        atomicAdd(&g_cnt[a][r4.y], 1);
        atomicAdd(&g_cnt[a][r4.z], 1);
        atomicAdd(&g_cnt[a][r4.w], 1);
    } else {
        for (int e = e0; e < E; e++)
            atomicAdd(&g_cnt[a][__ldg(erow + e)], 1);
    }
}

// ---------------------------------------------------------------------------
// exclusive prefix scan over g_cnt -> g_rptr (and g_head copy)
// one block per adjacency, 1024 threads, ~100 items/thread
// ---------------------------------------------------------------------------
__global__ __launch_bounds__(1024) void scan_kernel() {
    const int a = blockIdx.x;
    const int t = threadIdx.x;
    const int CH = (N_TOT + 1023) / 1024;   // 100
    const int base = t * CH;

    int s = 0;
    for (int i = 0; i < CH; i++) {
        int idx = base + i;
        if (idx < N_TOT) s += g_cnt[a][idx];
    }
    __shared__ int sh[1024];
    sh[t] = s;
    __syncthreads();
    for (int off = 1; off < 1024; off <<= 1) {
        int v = (t >= off) ? sh[t - off] : 0;
        __syncthreads();
        sh[t] += v;
        __syncthreads();
    }
    int run = (t == 0) ? 0 : sh[t - 1];
    for (int i = 0; i < CH; i++) {
        int idx = base + i;
        if (idx < N_TOT) {
            g_rptr[a][idx] = run;
            g_head[a][idx] = run;
            run += g_cnt[a][idx];
        }
    }
}

// ---------------------------------------------------------------------------
// place edge records (col, val) into CSR order
// ---------------------------------------------------------------------------
__global__ __launch_bounds__(256) void place_kernel(
    const int* __restrict__ erow1, const int* __restrict__ ecol1, const float* __restrict__ eval1,
    const int* __restrict__ erow2, const int* __restrict__ ecol2, const float* __restrict__ eval2,
    int E, int perAdj)
{
    int idx = blockIdx.x * blockDim.x + threadIdx.x;
    int a = 0;
    if (idx >= perAdj) { a = 1; idx -= perAdj; if (idx >= perAdj) return; }
    const int*   erow = a ? erow2 : erow1;
    const int*   ecol = a ? ecol2 : ecol1;
    const float* eval = a ? eval2 : eval1;
    unsigned long long* rec = g_rec[a];

    int e0 = idx * 4;
    if (e0 + 4 <= E) {
        int4   r4 = *(const int4*)(erow + e0);
        int4   c4 = *(const int4*)(ecol + e0);
        float4 v4 = *(const float4*)(eval + e0);
        int rr[4] = {r4.x, r4.y, r4.z, r4.w};
        int cc[4] = {c4.x, c4.y, c4.z, c4.w};
        float vv[4] = {v4.x, v4.y, v4.z, v4.w};
#pragma unroll
        for (int i = 0; i < 4; i++) {
            int pos = atomicAdd(&g_head[a][rr[i]], 1);
            rec[pos] = (unsigned long long)(unsigned)cc[i]
                     | ((unsigned long long)__float_as_uint(vv[i]) << 32);
        }
    } else {
        for (int e = e0; e < E; e++) {
            int r = __ldg(erow + e);
            int c = __ldg(ecol + e);
            float v = __ldg(eval + e);
            int pos = atomicAdd(&g_head[a][r], 1);
            rec[pos] = (unsigned long long)(unsigned)c
                     | ((unsigned long long)__float_as_uint(v) << 32);
        }
    }
}

// ---------------------------------------------------------------------------
// SpMM from CSR: one warp per output row, register accumulation, single store.
// Unroll 4 -> 4 independent gathers in flight.
// ---------------------------------------------------------------------------
__global__ __launch_bounds__(256) void spmm_kernel(
    const float* __restrict__ x1, float* __restrict__ x2, float* __restrict__ x3, int E)
{
    int gw = (int)(((size_t)blockIdx.x * blockDim.x + threadIdx.x) >> 5);
    if (gw >= 2 * N_TOT) return;
    const int lane = threadIdx.x & 31;
    const int a = (gw >= N_TOT) ? 1 : 0;
    const int r = a ? (gw - N_TOT) : gw;

    const unsigned long long* rec = g_rec[a];
    int start = g_rptr[a][r];
    int end   = (r + 1 < N_TOT) ? g_rptr[a][r + 1] : E;

    float4 acc = make_float4(0.f, 0.f, 0.f, 0.f);
    int j = start;
    for (; j + 4 <= end; j += 4) {
        unsigned long long q0 = __ldg(rec + j);
        unsigned long long q1 = __ldg(rec + j + 1);
        unsigned long long q2 = __ldg(rec + j + 2);
        unsigned long long q3 = __ldg(rec + j + 3);
        float4 p0 = __ldg((const float4*)(x1 + (size_t)(unsigned)(q0 & 0xffffffffu) * NDIM) + lane);
        float4 p1 = __ldg((const float4*)(x1 + (size_t)(unsigned)(q1 & 0xffffffffu) * NDIM) + lane);
        float4 p2 = __ldg((const float4*)(x1 + (size_t)(unsigned)(q2 & 0xffffffffu) * NDIM) + lane);
        float4 p3 = __ldg((const float4*)(x1 + (size_t)(unsigned)(q3 & 0xffffffffu) * NDIM) + lane);
        float v0 = __uint_as_float((unsigned)(q0 >> 32));
        float v1 = __uint_as_float((unsigned)(q1 >> 32));
        float v2 = __uint_as_float((unsigned)(q2 >> 32));
        float v3 = __uint_as_float((unsigned)(q3 >> 32));
        acc.x = fmaf(v0, p0.x, acc.x); acc.y = fmaf(v0, p0.y, acc.y);
        acc.z = fmaf(v0, p0.z, acc.z); acc.w = fmaf(v0, p0.w, acc.w);
        acc.x = fmaf(v1, p1.x, acc.x); acc.y = fmaf(v1, p1.y, acc.y);
        acc.z = fmaf(v1, p1.z, acc.z); acc.w = fmaf(v1, p1.w, acc.w);
        acc.x = fmaf(v2, p2.x, acc.x); acc.y = fmaf(v2, p2.y, acc.y);
        acc.z = fmaf(v2, p2.z, acc.z); acc.w = fmaf(v2, p2.w, acc.w);
        acc.x = fmaf(v3, p3.x, acc.x); acc.y = fmaf(v3, p3.y, acc.y);
        acc.z = fmaf(v3, p3.z, acc.z); acc.w = fmaf(v3, p3.w, acc.w);
    }
    for (; j < end; j++) {
        unsigned long long q = __ldg(rec + j);
        float4 p = __ldg((const float4*)(x1 + (size_t)(unsigned)(q & 0xffffffffu) * NDIM) + lane);
        float v = __uint_as_float((unsigned)(q >> 32));
        acc.x = fmaf(v, p.x, acc.x); acc.y = fmaf(v, p.y, acc.y);
        acc.z = fmaf(v, p.z, acc.z); acc.w = fmaf(v, p.w, acc.w);
    }

    float* out = (a ? x3 : x2) + (size_t)r * NDIM;
    ((float4*)out)[lane] = acc;
}

// ---------------------------------------------------------------------------
// SIMT fp32 GEMM (R2 version, known-good 163us)
// ---------------------------------------------------------------------------
__global__ __launch_bounds__(256) void gemm_kernel(
    const float* __restrict__ A0, const float* __restrict__ A1,
    const float* __restrict__ W, float* __restrict__ C)
{
    __shared__ float As[16][128 + 4];
    __shared__ float Ws[16][128 + 4];

    const int t  = threadIdx.x;
    const int tx = t & 15;
    const int ty = t >> 4;
    const int blockRow = blockIdx.x * 128;

    float acc[8][8];
#pragma unroll
    for (int i = 0; i < 8; i++)
#pragma unroll
        for (int j = 0; j < 8; j++) acc[i][j] = 0.f;

    for (int kk = 0; kk < NFEAT; kk += 16) {
#pragma unroll
        for (int l = 0; l < 2; l++) {
            int idx = t + l * 256;
            int r   = idx >> 2;
            int kq  = (idx & 3) << 2;

            int grow = blockRow + r;
            float4 v = make_float4(0.f, 0.f, 0.f, 0.f);
            if (grow < N_TOT) {
                const float* src = (grow < N_NODE)
                    ? (A0 + (size_t)grow * NFEAT)
                    : (A1 + (size_t)(grow - N_NODE) * NFEAT);
                v = *(const float4*)(src + kk + kq);
            }
            As[kq + 0][r] = v.x; As[kq + 1][r] = v.y;
            As[kq + 2][r] = v.z; As[kq + 3][r] = v.w;

            float4 w = *(const float4*)(W + (size_t)r * NFEAT + kk + kq);
            Ws[kq + 0][r] = w.x; Ws[kq + 1][r] = w.y;
            Ws[kq + 2][r] = w.z; Ws[kq + 3][r] = w.w;
        }
        __syncthreads();

#pragma unroll
        for (int k = 0; k < 16; k++) {
            float a[8], b[8];
#pragma unroll
            for (int i = 0; i < 4; i++) {
                a[i]     = As[k][ty * 4 + i];
                a[i + 4] = As[k][64 + ty * 4 + i];
                b[i]     = Ws[k][tx * 4 + i];
                b[i + 4] = Ws[k][64 + tx * 4 + i];
            }
#pragma unroll
            for (int i = 0; i < 8; i++)
#pragma unroll
                for (int j = 0; j < 8; j++)
                    acc[i][j] = fmaf(a[i], b[j], acc[i][j]);
        }
        __syncthreads();
    }

#pragma unroll
    for (int i = 0; i < 8; i++) {
        int rloc = (i < 4) ? (ty * 4 + i) : (64 + ty * 4 + (i - 4));
        int r = blockRow + rloc;
        if (r < N_TOT) {
            float* crow = C + (size_t)r * NDIM;
#pragma unroll
            for (int j = 0; j < 8; j++) {
                int cloc = (j < 4) ? (tx * 4 + j) : (64 + tx * 4 + (j - 4));
                crow[cloc] = acc[i][j];
            }
        }
    }
}

// ---------------------------------------------------------------------------
extern "C" void kernel_launch(void* const* d_in, const int* in_sizes, int n_in,
                              void* d_out, int out_size)
{
    const float* emb_node  = (const float*)d_in[0];
    const float* emb_attri = (const float*)d_in[1];
    const float* W1        = (const float*)d_in[2];
    const int*   adj_row   = (const int*)d_in[3];
    const int*   adj_col   = (const int*)d_in[4];
    const float* adj_val   = (const float*)d_in[5];
    const int*   adj2_row  = (const int*)d_in[6];
    const int*   adj2_col  = (const int*)d_in[7];
    const float* adj2_val  = (const float*)d_in[8];

    float* out = (float*)d_out;
    float* x1 = out;
    float* x2 = out + (size_t)N_TOT * NDIM;
    float* x3 = x2  + (size_t)N_TOT * NDIM;

    const int E = in_sizes[3];

    // CSR build
    zero_cnt_kernel<<<208, 256>>>();
    int perAdj = (E + 3) / 4;
    int hblocks = (2 * perAdj + 255) / 256;
    hist_kernel<<<hblocks, 256>>>(adj_row, adj2_row, E, perAdj);
    scan_kernel<<<2, 1024>>>();
    place_kernel<<<hblocks, 256>>>(adj_row,  adj_col,  adj_val,
                                   adj2_row, adj2_col, adj2_val, E, perAdj);

    // x1 = x0 @ W1^T (independent of CSR build)
    gemm_kernel<<<(N_TOT + 127) / 128, 256>>>(emb_node, emb_attri, W1, x1);

    // SpMM: one warp per output row, both adjacencies
    long long threads = (long long)2 * N_TOT * 32;
    int sblocks = (int)((threads + 255) / 256);
    spmm_kernel<<<sblocks, 256>>>(x1, x2, x3, E);
}